// round 3
// baseline (speedup 1.0000x reference)
#include <cuda_runtime.h>
#include <math.h>

#define NTOK 65536
#define DDIM 128
#define NEXP 16
#define TOPK 3

#define ETILE 512     // tokens per expert-kernel CTA tile
#define CHUNK 32      // active tokens processed per pass

// scratch for importance partial sums: 64 blocks x 16 experts
__device__ float g_part[64 * NEXP];

// ---------------------------------------------------------------------------
// Gating kernel: per token compute gate = x@Wg + bg + noise*softplus(x@Wn+bn),
// top-3, softmax -> comb; also initialize logits with sum_k w_k * be[e_k].
// grid 512 x block 128 (one thread per token)
// NOTE: comb region of d_out is only 4-byte aligned -> scalar access only.
// ---------------------------------------------------------------------------
__global__ void __launch_bounds__(128) gating_kernel(
    const float* __restrict__ x, const float* __restrict__ noise,
    const float* __restrict__ Wg, const float* __restrict__ bg,
    const float* __restrict__ Wn, const float* __restrict__ bn,
    const float* __restrict__ be,
    float* __restrict__ logits, float* __restrict__ comb)
{
    __shared__ float WgT[NEXP * DDIM];   // [e][d] transposed for broadcast reads
    __shared__ float WnT[NEXP * DDIM];
    __shared__ float beS[NEXP * DDIM];   // [e][d]
    __shared__ float tw[128][3];
    __shared__ int   ti[128][3];

    int tid = threadIdx.x;
    for (int i = tid; i < NEXP * DDIM; i += 128) {
        int d = i / NEXP, e = i % NEXP;       // coalesced read of Wg/Wn [d][e]
        WgT[e * DDIM + d] = Wg[i];
        WnT[e * DDIM + d] = Wn[i];
        beS[i] = be[i];
    }
    __syncthreads();

    int n = blockIdx.x * 128 + tid;

    float g[NEXP], ng[NEXP];
    #pragma unroll
    for (int e = 0; e < NEXP; e++) { g[e] = bg[e]; ng[e] = bn[e]; }

    const float4* x4 = (const float4*)(x + (size_t)n * DDIM);
    #pragma unroll 2
    for (int d4 = 0; d4 < DDIM / 4; d4++) {
        float4 xv = x4[d4];
        #pragma unroll
        for (int e = 0; e < NEXP; e++) {
            float4 a = ((const float4*)(WgT + e * DDIM))[d4];
            g[e]  += xv.x * a.x + xv.y * a.y + xv.z * a.z + xv.w * a.w;
            float4 b = ((const float4*)(WnT + e * DDIM))[d4];
            ng[e] += xv.x * b.x + xv.y * b.y + xv.z * b.z + xv.w * b.w;
        }
    }

    // gate = g + noise * softplus(ng)  (reuse g as gate)
    const float* nz = noise + (size_t)n * NEXP;
    #pragma unroll
    for (int e = 0; e < NEXP; e++) {
        float v = ng[e];
        float sp = (v > 20.f) ? v : log1pf(expf(v));
        g[e] = g[e] + nz[e] * sp;
    }

    // top-3 (strict >, earlier index wins ties -> matches lax.top_k)
    float v0 = -INFINITY, v1 = -INFINITY, v2 = -INFINITY;
    int i0 = 0, i1 = 0, i2 = 0;
    #pragma unroll
    for (int e = 0; e < NEXP; e++) {
        float v = g[e];
        if (v > v0)      { v2 = v1; i2 = i1; v1 = v0; i1 = i0; v0 = v; i0 = e; }
        else if (v > v1) { v2 = v1; i2 = i1; v1 = v;  i1 = e; }
        else if (v > v2) { v2 = v;  i2 = e; }
    }

    // softmax over the 3 values
    float e1 = expf(v1 - v0), e2 = expf(v2 - v0);
    float s = 1.f + e1 + e2;
    float w0 = 1.f / s, w1 = e1 / s, w2 = e2 / s;

    // stash topk in smem for cooperative, coalesced writes
    tw[tid][0] = w0; tw[tid][1] = w1; tw[tid][2] = w2;
    ti[tid][0] = i0; ti[tid][1] = i1; ti[tid][2] = i2;
    __syncthreads();

    int base = blockIdx.x * 128;

    // cooperative scalar comb write: consecutive tid -> consecutive addrs
    for (int i = tid; i < 128 * NEXP; i += 128) {
        int t = i >> 4, e = i & 15;
        float v = (e == ti[t][0]) ? tw[t][0]
                : (e == ti[t][1]) ? tw[t][1]
                : (e == ti[t][2]) ? tw[t][2] : 0.f;
        comb[(size_t)(base + t) * NEXP + e] = v;
    }

    // cooperative bias write into logits (coalesced rows)
    for (int t = 0; t < 128; t++) {
        float a0 = tw[t][0], a1 = tw[t][1], a2 = tw[t][2];
        int b0 = ti[t][0], b1 = ti[t][1], b2 = ti[t][2];
        logits[(size_t)(base + t) * DDIM + tid] =
            a0 * beS[b0 * DDIM + tid] + a1 * beS[b1 * DDIM + tid] + a2 * beS[b2 * DDIM + tid];
    }
}

// ---------------------------------------------------------------------------
// Expert kernel: grid (NTOK/ETILE, NEXP), 256 threads.
// CTA handles one (token-tile, expert): compact active tokens, load We[e] to
// smem, compute w * (x @ We[e]) for active tokens, atomicAdd into logits.
// dyn smem: Wes[16384] + xs[CHUNK*129] + act_n[ETILE] + act_w[ETILE]
// ---------------------------------------------------------------------------
__global__ void __launch_bounds__(256) expert_kernel(
    const float* __restrict__ x, const float* __restrict__ We,
    const float* __restrict__ comb, float* __restrict__ logits)
{
    extern __shared__ float sm[];
    float* Wes   = sm;                        // 16384 floats  [d][f]
    float* xs    = Wes + DDIM * DDIM;         // CHUNK*129 floats (reused as ys)
    int*   act_n = (int*)(xs + CHUNK * 129);  // ETILE ints
    float* act_w = (float*)(act_n + ETILE);   // ETILE floats
    __shared__ int scnt;

    int tid = threadIdx.x;
    int e = blockIdx.y;
    int n0 = blockIdx.x * ETILE;

    if (tid == 0) scnt = 0;
    __syncthreads();

    for (int i = tid; i < ETILE; i += 256) {
        float w = comb[(size_t)(n0 + i) * NEXP + e];
        if (w > 0.f) {
            int p = atomicAdd(&scnt, 1);
            act_n[p] = n0 + i;
            act_w[p] = w;
        }
    }
    __syncthreads();
    int cnt = scnt;
    if (cnt == 0) return;

    // stage We[e] (64KB) into smem, coalesced float4 copy
    {
        const float4* src = (const float4*)(We + (size_t)e * DDIM * DDIM);
        float4* dst = (float4*)Wes;
        #pragma unroll 4
        for (int i = tid; i < DDIM * DDIM / 4; i += 256) dst[i] = src[i];
    }
    __syncthreads();

    int tt = tid & 31;        // token slot within chunk
    int fg = tid >> 5;        // 8 f-groups of 16 outputs
    int fb = fg * 16;

    for (int c0 = 0; c0 < cnt; c0 += CHUNK) {
        int m = min(CHUNK, cnt - c0);

        // gather x rows of this chunk (coalesced 512B rows)
        for (int i = tid; i < m * DDIM; i += 256) {
            int a = i >> 7, f = i & 127;
            xs[a * 129 + f] = x[(size_t)act_n[c0 + a] * DDIM + f];
        }
        __syncthreads();

        float acc[16];
        #pragma unroll
        for (int j = 0; j < 16; j++) acc[j] = 0.f;

        const float* xr = xs + tt * 129;               // stride-129: conflict-free
        const float4* pW = (const float4*)(Wes + fb);  // warp-uniform: broadcast LDS
        #pragma unroll 4
        for (int d = 0; d < DDIM; d++) {
            float xv = xr[d];
            float4 a = pW[0], b = pW[1], c = pW[2], w = pW[3];
            acc[0]  += xv * a.x; acc[1]  += xv * a.y; acc[2]  += xv * a.z; acc[3]  += xv * a.w;
            acc[4]  += xv * b.x; acc[5]  += xv * b.y; acc[6]  += xv * b.z; acc[7]  += xv * b.w;
            acc[8]  += xv * c.x; acc[9]  += xv * c.y; acc[10] += xv * c.z; acc[11] += xv * c.w;
            acc[12] += xv * w.x; acc[13] += xv * w.y; acc[14] += xv * w.z; acc[15] += xv * w.w;
            pW += DDIM / 4;
        }
        __syncthreads();   // xs reads done; safe to reuse as y staging

        if (tt < m) {
            float wgt = act_w[c0 + tt];
            float* yr = xs + tt * 129 + fb;
            #pragma unroll
            for (int j = 0; j < 16; j++) yr[j] = wgt * acc[j];
        }
        __syncthreads();

        // coalesced atomic accumulate into logits
        for (int i = tid; i < m * DDIM; i += 256) {
            int a = i >> 7, f = i & 127;
            atomicAdd(&logits[(size_t)act_n[c0 + a] * DDIM + f], xs[a * 129 + f]);
        }
        __syncthreads();
    }
}

// ---------------------------------------------------------------------------
// Importance partials: imp_partial[block][e] = sum over 1024 tokens of comb
// grid 64 x block 256. Deterministic tree reduction. Scalar comb loads
// (comb region is only 4B aligned).
// ---------------------------------------------------------------------------
__global__ void __launch_bounds__(256) imp_kernel(
    const float* __restrict__ comb, float* __restrict__ part)
{
    __shared__ float red[NEXP][264];
    int tid = threadIdx.x;
    float p[NEXP];
    #pragma unroll
    for (int e = 0; e < NEXP; e++) p[e] = 0.f;

    int base = blockIdx.x * 1024;
    for (int k = 0; k < 4; k++) {
        int n = base + k * 256 + tid;
        const float* c = comb + (size_t)n * NEXP;
        #pragma unroll
        for (int e = 0; e < NEXP; e++) p[e] += c[e];
    }
    #pragma unroll
    for (int e = 0; e < NEXP; e++) red[e][tid] = p[e];
    __syncthreads();
    for (int s = 128; s >= 1; s >>= 1) {
        if (tid < s) {
            #pragma unroll
            for (int e = 0; e < NEXP; e++) red[e][tid] += red[e][tid + s];
        }
        __syncthreads();
    }
    if (tid < NEXP) part[blockIdx.x * NEXP + tid] = red[tid][0];
}

// final: imp_vec -> (std(ddof=1)/mean)^2
__global__ void loss_kernel(const float* __restrict__ part, float* __restrict__ out_loss)
{
    __shared__ float imp[NEXP];
    int tid = threadIdx.x;
    if (tid < NEXP) {
        float s = 0.f;
        for (int b = 0; b < 64; b++) s += part[b * NEXP + tid];
        imp[tid] = s;
    }
    __syncthreads();
    if (tid == 0) {
        float mean = 0.f;
        for (int e = 0; e < NEXP; e++) mean += imp[e];
        mean /= (float)NEXP;
        float var = 0.f;
        for (int e = 0; e < NEXP; e++) {
            float d = imp[e] - mean;
            var += d * d;
        }
        var /= (float)(NEXP - 1);
        out_loss[0] = var / (mean * mean);
    }
}

// ---------------------------------------------------------------------------
extern "C" void kernel_launch(void* const* d_in, const int* in_sizes, int n_in,
                              void* d_out, int out_size)
{
    const float* x     = (const float*)d_in[0];
    const float* noise = (const float*)d_in[1];
    const float* Wg    = (const float*)d_in[2];
    const float* bg    = (const float*)d_in[3];
    const float* Wn    = (const float*)d_in[4];
    const float* bn    = (const float*)d_in[5];
    const float* We    = (const float*)d_in[6];
    const float* be    = (const float*)d_in[7];

    float* out    = (float*)d_out;
    float* logits = out;                               // [N, D]
    float* lossp  = out + (size_t)NTOK * DDIM;         // scalar
    float* comb   = lossp + 1;                         // [N, E] (4B-aligned only!)

    float* part;
    cudaGetSymbolAddress((void**)&part, g_part);

    const int EXPERT_SMEM = (DDIM * DDIM + CHUNK * 129) * 4 + ETILE * 8;
    cudaFuncSetAttribute(expert_kernel,
                         cudaFuncAttributeMaxDynamicSharedMemorySize, EXPERT_SMEM);

    gating_kernel<<<NTOK / 128, 128>>>(x, noise, Wg, bg, Wn, bn, be, logits, comb);

    dim3 eg(NTOK / ETILE, NEXP);
    expert_kernel<<<eg, 256, EXPERT_SMEM>>>(x, We, comb, logits);

    imp_kernel<<<64, 256>>>(comb, part);
    loss_kernel<<<1, 32>>>(part, lossp);

    (void)in_sizes; (void)n_in; (void)out_size;
}

// round 5
// speedup vs baseline: 1.2535x; 1.2535x over previous
#include <cuda_runtime.h>
#include <cuda_bf16.h>
#include <math.h>
#include <stdint.h>

#define NTOK 65536
#define DDIM 128
#define NEXP 16
#define TOPK 3

#define KPAD 136              // bf16 elements per padded row (272 bytes)
#define ROWB 272              // bytes per padded row

// ---------------------------------------------------------------------------
// Device globals (static scratch; no runtime allocation allowed)
// ---------------------------------------------------------------------------
__device__ int      g_cnt[NEXP];
__device__ unsigned g_list[NEXP * NTOK];                 // (token<<2)|slot
__device__ float    g_wlist[NEXP * NTOK];
__device__ __nv_bfloat16 g_Bhi[NEXP * DDIM * KPAD];      // padded [e][n][k]
__device__ __nv_bfloat16 g_Blo[NEXP * DDIM * KPAD];
__device__ float    g_ybuf[(size_t)NTOK * TOPK * DDIM];  // 96MB partial outputs
__device__ float    g_part[64 * NEXP];

// ---------------------------------------------------------------------------
// helpers
// ---------------------------------------------------------------------------
__device__ __forceinline__ uint32_t smem_u32(const void* p) {
    uint32_t a;
    asm("{ .reg .u64 t; cvta.to.shared.u64 t, %1; cvt.u32.u64 %0, t; }" : "=r"(a) : "l"(p));
    return a;
}

#define LDSM_X4(r0, r1, r2, r3, addr) \
    asm volatile("ldmatrix.sync.aligned.m8n8.x4.shared.b16 {%0,%1,%2,%3}, [%4];" \
                 : "=r"(r0), "=r"(r1), "=r"(r2), "=r"(r3) : "r"(addr))

__device__ __forceinline__ void mma16816(float* c,
    uint32_t a0, uint32_t a1, uint32_t a2, uint32_t a3, uint32_t b0, uint32_t b1)
{
    asm volatile(
        "mma.sync.aligned.m16n8k16.row.col.f32.bf16.bf16.f32 "
        "{%0,%1,%2,%3}, {%4,%5,%6,%7}, {%8,%9}, {%0,%1,%2,%3};"
        : "+f"(c[0]), "+f"(c[1]), "+f"(c[2]), "+f"(c[3])
        : "r"(a0), "r"(a1), "r"(a2), "r"(a3), "r"(b0), "r"(b1));
}

// ---------------------------------------------------------------------------
// prepB: build padded bf16 hi/lo images of We^T ([n][k] row-major, K padded).
// Also zeroes g_cnt. grid (16, 4) x 256
// ---------------------------------------------------------------------------
__global__ void __launch_bounds__(256) prepB_kernel(const float* __restrict__ We)
{
    if (blockIdx.x == 0 && blockIdx.y == 0 && threadIdx.x < NEXP)
        g_cnt[threadIdx.x] = 0;

    int e = blockIdx.x;
    const float* W = We + (size_t)e * DDIM * DDIM;
    __nv_bfloat16* dsth = g_Bhi + (size_t)e * DDIM * KPAD;
    __nv_bfloat16* dstl = g_Blo + (size_t)e * DDIM * KPAD;
    int i0 = blockIdx.y * 2048 + threadIdx.x;
    for (int i = i0; i < (blockIdx.y + 1) * 2048; i += 256) {
        int n = i >> 6, kp = i & 63, k = kp * 2;   // n=output col, k=input dim
        float v0 = W[k * DDIM + n];
        float v1 = W[(k + 1) * DDIM + n];
        __nv_bfloat16 h0 = __float2bfloat16(v0);
        __nv_bfloat16 h1 = __float2bfloat16(v1);
        __nv_bfloat162 hp; hp.x = h0; hp.y = h1;
        __nv_bfloat162 lp;
        lp.x = __float2bfloat16(v0 - __bfloat162float(h0));
        lp.y = __float2bfloat16(v1 - __bfloat162float(h1));
        *(__nv_bfloat162*)(dsth + n * KPAD + k) = hp;
        *(__nv_bfloat162*)(dstl + n * KPAD + k) = lp;
    }
}

// ---------------------------------------------------------------------------
// Gating: gate = x@Wg + bg + noise*softplus(x@Wn+bn); top-3; softmax -> comb;
// logits := sum_k w_k*be[e_k]; build per-expert routing lists.
// grid 512 x 128
// ---------------------------------------------------------------------------
__global__ void __launch_bounds__(128) gating_kernel(
    const float* __restrict__ x, const float* __restrict__ noise,
    const float* __restrict__ Wg, const float* __restrict__ bg,
    const float* __restrict__ Wn, const float* __restrict__ bn,
    const float* __restrict__ be,
    float* __restrict__ logits, float* __restrict__ comb)
{
    __shared__ float WgT[NEXP * DDIM];
    __shared__ float WnT[NEXP * DDIM];
    __shared__ float beS[NEXP * DDIM];
    __shared__ float tw[128][3];
    __shared__ int   ti[128][3];
    __shared__ int   scnt16[NEXP];
    __shared__ int   gbase[NEXP];

    int tid = threadIdx.x;
    if (tid < NEXP) scnt16[tid] = 0;
    for (int i = tid; i < NEXP * DDIM; i += 128) {
        int d = i / NEXP, e = i % NEXP;
        WgT[e * DDIM + d] = Wg[i];
        WnT[e * DDIM + d] = Wn[i];
        beS[i] = be[i];
    }
    __syncthreads();

    int n = blockIdx.x * 128 + tid;

    float g[NEXP], ng[NEXP];
    #pragma unroll
    for (int e = 0; e < NEXP; e++) { g[e] = bg[e]; ng[e] = bn[e]; }

    const float4* x4 = (const float4*)(x + (size_t)n * DDIM);
    #pragma unroll 2
    for (int d4 = 0; d4 < DDIM / 4; d4++) {
        float4 xv = x4[d4];
        #pragma unroll
        for (int e = 0; e < NEXP; e++) {
            float4 a = ((const float4*)(WgT + e * DDIM))[d4];
            g[e]  += xv.x * a.x + xv.y * a.y + xv.z * a.z + xv.w * a.w;
            float4 b = ((const float4*)(WnT + e * DDIM))[d4];
            ng[e] += xv.x * b.x + xv.y * b.y + xv.z * b.z + xv.w * b.w;
        }
    }

    const float* nz = noise + (size_t)n * NEXP;
    #pragma unroll
    for (int e = 0; e < NEXP; e++) {
        float v = ng[e];
        float sp = (v > 20.f) ? v : log1pf(expf(v));
        g[e] = g[e] + nz[e] * sp;
    }

    float v0 = -INFINITY, v1 = -INFINITY, v2 = -INFINITY;
    int i0 = 0, i1 = 0, i2 = 0;
    #pragma unroll
    for (int e = 0; e < NEXP; e++) {
        float v = g[e];
        if (v > v0)      { v2 = v1; i2 = i1; v1 = v0; i1 = i0; v0 = v; i0 = e; }
        else if (v > v1) { v2 = v1; i2 = i1; v1 = v;  i1 = e; }
        else if (v > v2) { v2 = v;  i2 = e; }
    }

    float e1 = expf(v1 - v0), e2 = expf(v2 - v0);
    float s = 1.f + e1 + e2;
    float w0 = 1.f / s, w1 = e1 / s, w2 = e2 / s;

    // local routing positions
    int p0 = atomicAdd(&scnt16[i0], 1);
    int p1 = atomicAdd(&scnt16[i1], 1);
    int p2 = atomicAdd(&scnt16[i2], 1);

    tw[tid][0] = w0; tw[tid][1] = w1; tw[tid][2] = w2;
    ti[tid][0] = i0; ti[tid][1] = i1; ti[tid][2] = i2;
    __syncthreads();

    if (tid < NEXP) gbase[tid] = atomicAdd(&g_cnt[tid], scnt16[tid]);
    __syncthreads();

    {
        int q0 = gbase[i0] + p0;
        int q1 = gbase[i1] + p1;
        int q2 = gbase[i2] + p2;
        g_list[i0 * NTOK + q0] = ((unsigned)n << 2) | 0u;  g_wlist[i0 * NTOK + q0] = w0;
        g_list[i1 * NTOK + q1] = ((unsigned)n << 2) | 1u;  g_wlist[i1 * NTOK + q1] = w1;
        g_list[i2 * NTOK + q2] = ((unsigned)n << 2) | 2u;  g_wlist[i2 * NTOK + q2] = w2;
    }

    int base = blockIdx.x * 128;

    // scalar comb writes (comb region only 4B aligned)
    for (int i = tid; i < 128 * NEXP; i += 128) {
        int t = i >> 4, e = i & 15;
        float v = (e == ti[t][0]) ? tw[t][0]
                : (e == ti[t][1]) ? tw[t][1]
                : (e == ti[t][2]) ? tw[t][2] : 0.f;
        comb[(size_t)(base + t) * NEXP + e] = v;
    }

    // bias combination into logits (coalesced rows)
    for (int t = 0; t < 128; t++) {
        float a0 = tw[t][0], a1 = tw[t][1], a2 = tw[t][2];
        int b0 = ti[t][0], b1 = ti[t][1], b2 = ti[t][2];
        logits[(size_t)(base + t) * DDIM + tid] =
            a0 * beS[b0 * DDIM + tid] + a1 * beS[b1 * DDIM + tid] + a2 * beS[b2 * DDIM + tid];
    }
}

// ---------------------------------------------------------------------------
// MoE GEMM via mma.sync bf16 (3-term split, fp32 accum).
// grid (128, NEXP) x 256 threads (8 warps, 4M x 2N, 32x64 warp tiles).
// dyn smem (bytes):
//   [0,34816)        B_hi   [34816,69632)  B_lo
//   [69632,104448)   A_hi   [104448,139264) A_lo
//     (A region reused as 128x132 f32 epilogue buffer)
//   [139264,139776)  ent[128]   [139776,140288) w[128]
// ---------------------------------------------------------------------------
#define SM_BHI 0
#define SM_BLO 34816
#define SM_AHI 69632
#define SM_ALO 104448
#define SM_EPI 69632
#define SM_ENT 139264
#define SM_W   139776
#define SM_SZ  140288

__global__ void __launch_bounds__(256) moe_gemm_kernel(const float* __restrict__ x)
{
    extern __shared__ char smp[];
    uint32_t base = smem_u32(smp);

    int tid = threadIdx.x, wp = tid >> 5, ln = tid & 31;
    int e = blockIdx.y;
    int cnt = g_cnt[e];
    int ntile = (cnt + 127) >> 7;
    if ((int)blockIdx.x >= ntile) return;

    // stage pre-split B images (plain copy, padded rows)
    {
        const float4* bh = (const float4*)(g_Bhi + (size_t)e * DDIM * KPAD);
        const float4* bl = (const float4*)(g_Blo + (size_t)e * DDIM * KPAD);
        float4* dh = (float4*)(smp + SM_BHI);
        float4* dl = (float4*)(smp + SM_BLO);
        #pragma unroll 4
        for (int i = tid; i < DDIM * ROWB / 16; i += 256) { dh[i] = bh[i]; dl[i] = bl[i]; }
    }

    unsigned* entS = (unsigned*)(smp + SM_ENT);
    float*    wS   = (float*)(smp + SM_W);
    float*    epi  = (float*)(smp + SM_EPI);

    int mrow = (wp & 3) * 32;       // warp M origin (two m16 tiles)
    int ncol = (wp >> 2) * 64;      // warp N origin (8 n8 tiles)

    // per-lane ldmatrix byte offsets (within a panel)
    uint32_t a_off = (uint32_t)(mrow + (ln & 15)) * ROWB + ((ln >> 4) << 4);
    uint32_t b_off = (uint32_t)(ncol + (ln & 7) + ((ln >> 4) << 3)) * ROWB + (((ln >> 3) & 1) << 4);

    for (int t = blockIdx.x; t < ntile; t += gridDim.x) {
        int rbase = t << 7;
        int mvalid = min(128, cnt - rbase);

        if (tid < 128) {
            if (tid < mvalid) {
                entS[tid] = g_list[e * NTOK + rbase + tid];
                wS[tid]   = g_wlist[e * NTOK + rbase + tid];
            } else { entS[tid] = 0xFFFFFFFFu; wS[tid] = 0.f; }
        }
        __syncthreads();

        // build A hi/lo panels (gather + split), padded row-major
        for (int i = tid; i < 8192; i += 256) {
            int m = i >> 6, kp = i & 63;
            unsigned en = entS[m];
            uint32_t hv = 0, lv = 0;
            if (en != 0xFFFFFFFFu) {
                float2 v = *(const float2*)(x + (size_t)(en >> 2) * DDIM + kp * 2);
                __nv_bfloat16 h0 = __float2bfloat16(v.x);
                __nv_bfloat16 h1 = __float2bfloat16(v.y);
                __nv_bfloat162 hp; hp.x = h0; hp.y = h1;
                __nv_bfloat162 lp;
                lp.x = __float2bfloat16(v.x - __bfloat162float(h0));
                lp.y = __float2bfloat16(v.y - __bfloat162float(h1));
                hv = *(uint32_t*)&hp; lv = *(uint32_t*)&lp;
            }
            uint32_t ro = (uint32_t)m * ROWB + (uint32_t)kp * 4;
            *(uint32_t*)(smp + SM_AHI + ro) = hv;
            *(uint32_t*)(smp + SM_ALO + ro) = lv;
        }
        __syncthreads();

        float c[2][8][4];
        #pragma unroll
        for (int i = 0; i < 2; i++)
            #pragma unroll
            for (int j = 0; j < 8; j++)
                #pragma unroll
                for (int q = 0; q < 4; q++) c[i][j][q] = 0.f;

        const uint32_t aps[3] = { base + SM_AHI, base + SM_AHI, base + SM_ALO };
        const uint32_t bps[3] = { base + SM_BHI, base + SM_BLO, base + SM_BHI };

        #pragma unroll
        for (int term = 0; term < 3; term++) {
            uint32_t ab = aps[term] + a_off;
            uint32_t bb = bps[term] + b_off;
            #pragma unroll
            for (int kk = 0; kk < 8; kk++) {
                uint32_t kb = (uint32_t)kk * 32;    // k16 step = 32 bytes
                uint32_t a0, a1, a2, a3, a4, a5, a6, a7;
                LDSM_X4(a0, a1, a2, a3, ab + kb);              // m-tile 0
                LDSM_X4(a4, a5, a6, a7, ab + 16 * ROWB + kb);  // m-tile 1
                #pragma unroll
                for (int nw = 0; nw < 4; nw++) {               // n16 windows
                    uint32_t b0, b1, b2, b3;
                    LDSM_X4(b0, b1, b2, b3, bb + (uint32_t)nw * 16 * ROWB + kb);
                    mma16816(c[0][nw * 2 + 0], a0, a1, a2, a3, b0, b1);
                    mma16816(c[0][nw * 2 + 1], a0, a1, a2, a3, b2, b3);
                    mma16816(c[1][nw * 2 + 0], a4, a5, a6, a7, b0, b1);
                    mma16816(c[1][nw * 2 + 1], a4, a5, a6, a7, b2, b3);
                }
            }
        }
        __syncthreads();   // all mma done; A region reusable as epilogue buffer

        // scale by routing weight, stage to smem (fragment layout -> rows)
        {
            int gid = ln >> 2, tig = ln & 3;
            #pragma unroll
            for (int mt = 0; mt < 2; mt++) {
                int r0 = mrow + mt * 16 + gid;
                int r1 = r0 + 8;
                float wa = wS[r0], wb = wS[r1];
                #pragma unroll
                for (int nt = 0; nt < 8; nt++) {
                    int col = ncol + nt * 8 + tig * 2;
                    float2 va; va.x = c[mt][nt][0] * wa; va.y = c[mt][nt][1] * wa;
                    float2 vb; vb.x = c[mt][nt][2] * wb; vb.y = c[mt][nt][3] * wb;
                    *(float2*)(epi + r0 * 132 + col) = va;
                    *(float2*)(epi + r1 * 132 + col) = vb;
                }
            }
        }
        __syncthreads();

        // coalesced copy-out to ybuf[token][slot][:]
        for (int i = tid; i < 4096; i += 256) {
            int r = i >> 5, c4 = i & 31;
            unsigned en = entS[r];
            if (en != 0xFFFFFFFFu) {
                float4 v = *(const float4*)(epi + r * 132 + c4 * 4);
                *(float4*)(g_ybuf + ((size_t)(en >> 2) * 3 + (en & 3u)) * DDIM + c4 * 4) = v;
            }
        }
        __syncthreads();
    }
}

// ---------------------------------------------------------------------------
// Combine: logits[n] += ybuf[n][0]+[1]+[2]   (bias combo already in logits)
// ---------------------------------------------------------------------------
__global__ void __launch_bounds__(256) combine_kernel(float* __restrict__ logits)
{
    size_t idx = (size_t)blockIdx.x * 256 + threadIdx.x;   // over N*32 float4
    int n = (int)(idx >> 5), c = (int)(idx & 31);
    float4 a = ((float4*)logits)[idx];
    const float4* y = (const float4*)(g_ybuf + (size_t)n * 3 * DDIM);
    float4 p0 = y[c], p1 = y[32 + c], p2 = y[64 + c];
    a.x += p0.x + p1.x + p2.x;
    a.y += p0.y + p1.y + p2.y;
    a.z += p0.z + p1.z + p2.z;
    a.w += p0.w + p1.w + p2.w;
    ((float4*)logits)[idx] = a;
}

// ---------------------------------------------------------------------------
// Importance partials + loss
// ---------------------------------------------------------------------------
__global__ void __launch_bounds__(256) imp_kernel(
    const float* __restrict__ comb, float* __restrict__ part)
{
    __shared__ float red[NEXP][264];
    int tid = threadIdx.x;
    float p[NEXP];
    #pragma unroll
    for (int e = 0; e < NEXP; e++) p[e] = 0.f;

    int base = blockIdx.x * 1024;
    for (int k = 0; k < 4; k++) {
        int n = base + k * 256 + tid;
        const float* c = comb + (size_t)n * NEXP;
        #pragma unroll
        for (int e = 0; e < NEXP; e++) p[e] += c[e];
    }
    #pragma unroll
    for (int e = 0; e < NEXP; e++) red[e][tid] = p[e];
    __syncthreads();
    for (int s = 128; s >= 1; s >>= 1) {
        if (tid < s) {
            #pragma unroll
            for (int e = 0; e < NEXP; e++) red[e][tid] += red[e][tid + s];
        }
        __syncthreads();
    }
    if (tid < NEXP) part[blockIdx.x * NEXP + tid] = red[tid][0];
}

__global__ void loss_kernel(const float* __restrict__ part, float* __restrict__ out_loss)
{
    __shared__ float imp[NEXP];
    int tid = threadIdx.x;
    if (tid < NEXP) {
        float s = 0.f;
        for (int b = 0; b < 64; b++) s += part[b * NEXP + tid];
        imp[tid] = s;
    }
    __syncthreads();
    if (tid == 0) {
        float mean = 0.f;
        for (int e = 0; e < NEXP; e++) mean += imp[e];
        mean /= (float)NEXP;
        float var = 0.f;
        for (int e = 0; e < NEXP; e++) {
            float d = imp[e] - mean;
            var += d * d;
        }
        var /= (float)(NEXP - 1);
        out_loss[0] = var / (mean * mean);
    }
}

// ---------------------------------------------------------------------------
extern "C" void kernel_launch(void* const* d_in, const int* in_sizes, int n_in,
                              void* d_out, int out_size)
{
    const float* x     = (const float*)d_in[0];
    const float* noise = (const float*)d_in[1];
    const float* Wg    = (const float*)d_in[2];
    const float* bg    = (const float*)d_in[3];
    const float* Wn    = (const float*)d_in[4];
    const float* bn    = (const float*)d_in[5];
    const float* We    = (const float*)d_in[6];
    const float* be    = (const float*)d_in[7];

    float* out    = (float*)d_out;
    float* logits = out;                               // [N, D]
    float* lossp  = out + (size_t)NTOK * DDIM;         // scalar
    float* comb   = lossp + 1;                         // [N, E] (4B aligned only)

    float* part;  cudaGetSymbolAddress((void**)&part, g_part);

    prepB_kernel<<<dim3(NEXP, 4), 256>>>(We);          // also zeroes g_cnt

    gating_kernel<<<NTOK / 128, 128>>>(x, noise, Wg, bg, Wn, bn, be, logits, comb);

    cudaFuncSetAttribute(moe_gemm_kernel,
                         cudaFuncAttributeMaxDynamicSharedMemorySize, SM_SZ);
    moe_gemm_kernel<<<dim3(128, NEXP), 256, SM_SZ>>>(x);

    combine_kernel<<<(NTOK * DDIM / 4) / 256, 256>>>(logits);

    imp_kernel<<<64, 256>>>(comb, part);
    loss_kernel<<<1, 32>>>(part, lossp);

    (void)in_sizes; (void)n_in; (void)out_size;
}

// round 6
// speedup vs baseline: 2.0326x; 1.6215x over previous
#include <cuda_runtime.h>
#include <cuda_fp16.h>
#include <math.h>
#include <stdint.h>

#define NTOK 65536
#define DDIM 128
#define NEXP 16
#define TOPK 3

#define KPAD 136              // fp16 elements per padded row
#define ROWB 272              // bytes per padded row

// ---------------------------------------------------------------------------
// Device globals (static scratch; no runtime allocation allowed)
// ---------------------------------------------------------------------------
__device__ int      g_cnt[NEXP];
__device__ unsigned g_list[NEXP * NTOK];                 // (token<<2)|slot
__device__ float    g_wlist[NEXP * NTOK];
__device__ __half   g_Bh[NEXP * DDIM * KPAD];            // padded fp16 [e][n][k]
__device__ float    g_ybuf[(size_t)NTOK * TOPK * DDIM];  // 96MB partial outputs
__device__ float    g_part[64 * NEXP];

// ---------------------------------------------------------------------------
// helpers
// ---------------------------------------------------------------------------
__device__ __forceinline__ uint32_t smem_u32(const void* p) {
    uint32_t a;
    asm("{ .reg .u64 t; cvta.to.shared.u64 t, %1; cvt.u32.u64 %0, t; }" : "=r"(a) : "l"(p));
    return a;
}

#define LDSM_X4(r0, r1, r2, r3, addr) \
    asm volatile("ldmatrix.sync.aligned.m8n8.x4.shared.b16 {%0,%1,%2,%3}, [%4];" \
                 : "=r"(r0), "=r"(r1), "=r"(r2), "=r"(r3) : "r"(addr))

__device__ __forceinline__ void mma16816(float* c,
    uint32_t a0, uint32_t a1, uint32_t a2, uint32_t a3, uint32_t b0, uint32_t b1)
{
    asm volatile(
        "mma.sync.aligned.m16n8k16.row.col.f32.f16.f16.f32 "
        "{%0,%1,%2,%3}, {%4,%5,%6,%7}, {%8,%9}, {%0,%1,%2,%3};"
        : "+f"(c[0]), "+f"(c[1]), "+f"(c[2]), "+f"(c[3])
        : "r"(a0), "r"(a1), "r"(a2), "r"(a3), "r"(b0), "r"(b1));
}

// ---------------------------------------------------------------------------
// prepB: padded fp16 image of We^T ([e][n][k] row-major). Zeroes g_cnt.
// grid (16, 4) x 256
// ---------------------------------------------------------------------------
__global__ void __launch_bounds__(256) prepB_kernel(const float* __restrict__ We)
{
    if (blockIdx.x == 0 && blockIdx.y == 0 && threadIdx.x < NEXP)
        g_cnt[threadIdx.x] = 0;

    int e = blockIdx.x;
    const float* W = We + (size_t)e * DDIM * DDIM;
    __half* dst = g_Bh + (size_t)e * DDIM * KPAD;
    int i0 = blockIdx.y * 2048 + threadIdx.x;
    for (int i = i0; i < (blockIdx.y + 1) * 2048; i += 256) {
        int n = i >> 6, kp = i & 63, k = kp * 2;   // n=output col, k=input dim
        __half2 hp;
        hp.x = __float2half(W[k * DDIM + n]);
        hp.y = __float2half(W[(k + 1) * DDIM + n]);
        *(__half2*)(dst + n * KPAD + k) = hp;
    }
}

// ---------------------------------------------------------------------------
// Gating: gate = x@Wg + bg + noise*softplus(x@Wn+bn); top-3; softmax -> comb;
// build per-expert routing lists. grid 512 x 128
// ---------------------------------------------------------------------------
__global__ void __launch_bounds__(128) gating_kernel(
    const float* __restrict__ x, const float* __restrict__ noise,
    const float* __restrict__ Wg, const float* __restrict__ bg,
    const float* __restrict__ Wn, const float* __restrict__ bn,
    float* __restrict__ comb)
{
    __shared__ float WgT[NEXP * DDIM];
    __shared__ float WnT[NEXP * DDIM];
    __shared__ float tw[128][3];
    __shared__ int   ti[128][3];
    __shared__ int   scnt16[NEXP];
    __shared__ int   gbase[NEXP];

    int tid = threadIdx.x;
    if (tid < NEXP) scnt16[tid] = 0;
    for (int i = tid; i < NEXP * DDIM; i += 128) {
        int d = i / NEXP, e = i % NEXP;
        WgT[e * DDIM + d] = Wg[i];
        WnT[e * DDIM + d] = Wn[i];
    }
    __syncthreads();

    int n = blockIdx.x * 128 + tid;

    float g[NEXP], ng[NEXP];
    #pragma unroll
    for (int e = 0; e < NEXP; e++) { g[e] = bg[e]; ng[e] = bn[e]; }

    const float4* x4 = (const float4*)(x + (size_t)n * DDIM);
    #pragma unroll 2
    for (int d4 = 0; d4 < DDIM / 4; d4++) {
        float4 xv = x4[d4];
        #pragma unroll
        for (int e = 0; e < NEXP; e++) {
            float4 a = ((const float4*)(WgT + e * DDIM))[d4];
            g[e]  += xv.x * a.x + xv.y * a.y + xv.z * a.z + xv.w * a.w;
            float4 b = ((const float4*)(WnT + e * DDIM))[d4];
            ng[e] += xv.x * b.x + xv.y * b.y + xv.z * b.z + xv.w * b.w;
        }
    }

    const float* nz = noise + (size_t)n * NEXP;
    #pragma unroll
    for (int e = 0; e < NEXP; e++) {
        float v = ng[e];
        float sp = (v > 20.f) ? v : log1pf(expf(v));
        g[e] = g[e] + nz[e] * sp;
    }

    float v0 = -INFINITY, v1 = -INFINITY, v2 = -INFINITY;
    int i0 = 0, i1 = 0, i2 = 0;
    #pragma unroll
    for (int e = 0; e < NEXP; e++) {
        float v = g[e];
        if (v > v0)      { v2 = v1; i2 = i1; v1 = v0; i1 = i0; v0 = v; i0 = e; }
        else if (v > v1) { v2 = v1; i2 = i1; v1 = v;  i1 = e; }
        else if (v > v2) { v2 = v;  i2 = e; }
    }

    float e1 = expf(v1 - v0), e2 = expf(v2 - v0);
    float s = 1.f + e1 + e2;
    float w0 = 1.f / s, w1 = e1 / s, w2 = e2 / s;

    int p0 = atomicAdd(&scnt16[i0], 1);
    int p1 = atomicAdd(&scnt16[i1], 1);
    int p2 = atomicAdd(&scnt16[i2], 1);

    tw[tid][0] = w0; tw[tid][1] = w1; tw[tid][2] = w2;
    ti[tid][0] = i0; ti[tid][1] = i1; ti[tid][2] = i2;
    __syncthreads();

    if (tid < NEXP) gbase[tid] = atomicAdd(&g_cnt[tid], scnt16[tid]);
    __syncthreads();

    {
        int q0 = gbase[i0] + p0;
        int q1 = gbase[i1] + p1;
        int q2 = gbase[i2] + p2;
        g_list[i0 * NTOK + q0] = ((unsigned)n << 2) | 0u;  g_wlist[i0 * NTOK + q0] = w0;
        g_list[i1 * NTOK + q1] = ((unsigned)n << 2) | 1u;  g_wlist[i1 * NTOK + q1] = w1;
        g_list[i2 * NTOK + q2] = ((unsigned)n << 2) | 2u;  g_wlist[i2 * NTOK + q2] = w2;
    }

    int base = blockIdx.x * 128;
    // scalar comb writes (comb region only 4B aligned)
    for (int i = tid; i < 128 * NEXP; i += 128) {
        int t = i >> 4, e = i & 15;
        float v = (e == ti[t][0]) ? tw[t][0]
                : (e == ti[t][1]) ? tw[t][1]
                : (e == ti[t][2]) ? tw[t][2] : 0.f;
        comb[(size_t)(base + t) * NEXP + e] = v;
    }
}

// ---------------------------------------------------------------------------
// MoE GEMM via mma.sync fp16 single-term (f32 accum).
// grid (128, NEXP) x 256 threads (8 warps, 4M x 2N, 32x64 warp tiles).
// smem: A[0,34816) B[34816,69632) ent[69632,+512) w[+512)  => 70656 bytes
// 2 CTAs/SM.
// ---------------------------------------------------------------------------
#define SM_A   0
#define SM_B   34816
#define SM_ENT 69632
#define SM_W   70144
#define SM_SZ  70656

__global__ void __launch_bounds__(256, 2) moe_gemm_kernel(const float* __restrict__ x)
{
    extern __shared__ char smp[];
    uint32_t base = smem_u32(smp);

    int tid = threadIdx.x, wp = tid >> 5, ln = tid & 31;
    int e = blockIdx.y;
    int cnt = g_cnt[e];
    int ntile = (cnt + 127) >> 7;
    if ((int)blockIdx.x >= ntile) return;

    // stage fp16 B image (plain copy, padded rows)
    {
        const float4* bs = (const float4*)(g_Bh + (size_t)e * DDIM * KPAD);
        float4* bd = (float4*)(smp + SM_B);
        #pragma unroll 4
        for (int i = tid; i < DDIM * ROWB / 16; i += 256) bd[i] = bs[i];
    }

    unsigned* entS = (unsigned*)(smp + SM_ENT);
    float*    wS   = (float*)(smp + SM_W);

    int mrow = (wp & 3) * 32;       // warp M origin (two m16 tiles)
    int ncol = (wp >> 2) * 64;      // warp N origin (8 n8 tiles)

    uint32_t a_off = (uint32_t)(mrow + (ln & 15)) * ROWB + ((ln >> 4) << 4);
    uint32_t b_off = (uint32_t)(ncol + (ln & 7) + ((ln >> 4) << 3)) * ROWB + (((ln >> 3) & 1) << 4);

    for (int t = blockIdx.x; t < ntile; t += gridDim.x) {
        int rbase = t << 7;
        int mvalid = min(128, cnt - rbase);

        if (tid < 128) {
            if (tid < mvalid) {
                entS[tid] = g_list[e * NTOK + rbase + tid];
                wS[tid]   = g_wlist[e * NTOK + rbase + tid];
            } else { entS[tid] = 0xFFFFFFFFu; wS[tid] = 0.f; }
        }
        __syncthreads();

        // build A panel (gather + fp16 cvt), padded row-major
        for (int i = tid; i < 8192; i += 256) {
            int m = i >> 6, kp = i & 63;
            unsigned en = entS[m];
            uint32_t hv = 0;
            if (en != 0xFFFFFFFFu) {
                float2 v = *(const float2*)(x + (size_t)(en >> 2) * DDIM + kp * 2);
                __half2 hp; hp.x = __float2half(v.x); hp.y = __float2half(v.y);
                hv = *(uint32_t*)&hp;
            }
            *(uint32_t*)(smp + SM_A + (uint32_t)m * ROWB + (uint32_t)kp * 4) = hv;
        }
        __syncthreads();

        float c[2][8][4];
        #pragma unroll
        for (int i = 0; i < 2; i++)
            #pragma unroll
            for (int j = 0; j < 8; j++)
                #pragma unroll
                for (int q = 0; q < 4; q++) c[i][j][q] = 0.f;

        uint32_t ab = base + SM_A + a_off;
        uint32_t bb = base + SM_B + b_off;
        #pragma unroll
        for (int kk = 0; kk < 8; kk++) {
            uint32_t kb = (uint32_t)kk * 32;    // k16 step = 32 bytes
            uint32_t a0, a1, a2, a3, a4, a5, a6, a7;
            LDSM_X4(a0, a1, a2, a3, ab + kb);              // m-tile 0
            LDSM_X4(a4, a5, a6, a7, ab + 16 * ROWB + kb);  // m-tile 1
            #pragma unroll
            for (int nw = 0; nw < 4; nw++) {               // n16 windows
                uint32_t b0, b1, b2, b3;
                LDSM_X4(b0, b1, b2, b3, bb + (uint32_t)nw * 16 * ROWB + kb);
                mma16816(c[0][nw * 2 + 0], a0, a1, a2, a3, b0, b1);
                mma16816(c[0][nw * 2 + 1], a0, a1, a2, a3, b2, b3);
                mma16816(c[1][nw * 2 + 0], a4, a5, a6, a7, b0, b1);
                mma16816(c[1][nw * 2 + 1], a4, a5, a6, a7, b2, b3);
            }
        }

        // epilogue: scale by routing weight, direct STG to ybuf (32B sectors)
        {
            int gid = ln >> 2, tig = ln & 3;
            #pragma unroll
            for (int mt = 0; mt < 2; mt++) {
                int r0 = mrow + mt * 16 + gid;
                int r1 = r0 + 8;
                unsigned e0 = entS[r0], e1 = entS[r1];
                float wa = wS[r0], wb = wS[r1];
                float* y0 = g_ybuf + ((size_t)(e0 >> 2) * 3 + (e0 & 3u)) * DDIM;
                float* y1 = g_ybuf + ((size_t)(e1 >> 2) * 3 + (e1 & 3u)) * DDIM;
                #pragma unroll
                for (int nt = 0; nt < 8; nt++) {
                    int col = ncol + nt * 8 + tig * 2;
                    if (e0 != 0xFFFFFFFFu) {
                        float2 va; va.x = c[mt][nt][0] * wa; va.y = c[mt][nt][1] * wa;
                        *(float2*)(y0 + col) = va;
                    }
                    if (e1 != 0xFFFFFFFFu) {
                        float2 vb; vb.x = c[mt][nt][2] * wb; vb.y = c[mt][nt][3] * wb;
                        *(float2*)(y1 + col) = vb;
                    }
                }
            }
        }
        __syncthreads();
    }
}

// ---------------------------------------------------------------------------
// Combine: logits[n] = sum_e comb[n][e]*be[e] + ybuf[n][0]+[1]+[2]
// grid 2048 x 256: block = 32 tokens; thread = 4 float4 of one token.
// ---------------------------------------------------------------------------
__global__ void __launch_bounds__(256) combine_kernel(
    const float* __restrict__ comb, const float* __restrict__ be,
    float* __restrict__ logits)
{
    __shared__ float beS[NEXP][DDIM];   // 8KB
    __shared__ float cS[32][NEXP + 1];

    int tid = threadIdx.x;
    int n0 = blockIdx.x * 32;

    for (int i = tid; i < NEXP * DDIM; i += 256) beS[i >> 7][i & 127] = be[i];
    for (int i = tid; i < 32 * NEXP; i += 256)
        cS[i >> 4][i & 15] = comb[(size_t)(n0 + (i >> 4)) * NEXP + (i & 15)];
    __syncthreads();

    int tok = tid >> 3, q = tid & 7;
    int n = n0 + tok;
    const float* y = g_ybuf + (size_t)n * 3 * DDIM;
    float* lrow = logits + (size_t)n * DDIM;

    #pragma unroll
    for (int j = 0; j < 4; j++) {
        int col = (q + j * 8) * 4;
        float4 a = *(const float4*)(y + col);
        float4 b = *(const float4*)(y + DDIM + col);
        float4 d = *(const float4*)(y + 2 * DDIM + col);
        a.x += b.x + d.x; a.y += b.y + d.y; a.z += b.z + d.z; a.w += b.w + d.w;
        #pragma unroll
        for (int e = 0; e < NEXP; e++) {
            float f = cS[tok][e];
            const float4 bv = *(const float4*)(&beS[e][col]);
            a.x += f * bv.x; a.y += f * bv.y; a.z += f * bv.z; a.w += f * bv.w;
        }
        *(float4*)(lrow + col) = a;
    }
}

// ---------------------------------------------------------------------------
// Importance partials + loss
// ---------------------------------------------------------------------------
__global__ void __launch_bounds__(256) imp_kernel(
    const float* __restrict__ comb, float* __restrict__ part)
{
    __shared__ float red[NEXP][264];
    int tid = threadIdx.x;
    float p[NEXP];
    #pragma unroll
    for (int e = 0; e < NEXP; e++) p[e] = 0.f;

    int base = blockIdx.x * 1024;
    for (int k = 0; k < 4; k++) {
        int n = base + k * 256 + tid;
        const float* c = comb + (size_t)n * NEXP;
        #pragma unroll
        for (int e = 0; e < NEXP; e++) p[e] += c[e];
    }
    #pragma unroll
    for (int e = 0; e < NEXP; e++) red[e][tid] = p[e];
    __syncthreads();
    for (int s = 128; s >= 1; s >>= 1) {
        if (tid < s) {
            #pragma unroll
            for (int e = 0; e < NEXP; e++) red[e][tid] += red[e][tid + s];
        }
        __syncthreads();
    }
    if (tid < NEXP) part[blockIdx.x * NEXP + tid] = red[tid][0];
}

__global__ void loss_kernel(const float* __restrict__ part, float* __restrict__ out_loss)
{
    __shared__ float imp[NEXP];
    int tid = threadIdx.x;
    if (tid < NEXP) {
        float s = 0.f;
        for (int b = 0; b < 64; b++) s += part[b * NEXP + tid];
        imp[tid] = s;
    }
    __syncthreads();
    if (tid == 0) {
        float mean = 0.f;
        for (int e = 0; e < NEXP; e++) mean += imp[e];
        mean /= (float)NEXP;
        float var = 0.f;
        for (int e = 0; e < NEXP; e++) {
            float d = imp[e] - mean;
            var += d * d;
        }
        var /= (float)(NEXP - 1);
        out_loss[0] = var / (mean * mean);
    }
}

// ---------------------------------------------------------------------------
extern "C" void kernel_launch(void* const* d_in, const int* in_sizes, int n_in,
                              void* d_out, int out_size)
{
    const float* x     = (const float*)d_in[0];
    const float* noise = (const float*)d_in[1];
    const float* Wg    = (const float*)d_in[2];
    const float* bg    = (const float*)d_in[3];
    const float* Wn    = (const float*)d_in[4];
    const float* bn    = (const float*)d_in[5];
    const float* We    = (const float*)d_in[6];
    const float* be    = (const float*)d_in[7];

    float* out    = (float*)d_out;
    float* logits = out;                               // [N, D]
    float* lossp  = out + (size_t)NTOK * DDIM;         // scalar
    float* comb   = lossp + 1;                         // [N, E] (4B aligned only)

    float* part;  cudaGetSymbolAddress((void**)&part, g_part);

    prepB_kernel<<<dim3(NEXP, 4), 256>>>(We);          // also zeroes g_cnt

    gating_kernel<<<NTOK / 128, 128>>>(x, noise, Wg, bg, Wn, bn, comb);

    cudaFuncSetAttribute(moe_gemm_kernel,
                         cudaFuncAttributeMaxDynamicSharedMemorySize, SM_SZ);
    moe_gemm_kernel<<<dim3(128, NEXP), 256, SM_SZ>>>(x);

    combine_kernel<<<NTOK / 32, 256>>>(comb, be, logits);

    imp_kernel<<<64, 256>>>(comb, part);
    loss_kernel<<<1, 32>>>(part, lossp);

    (void)in_sizes; (void)n_in; (void)out_size;
}

// round 7
// speedup vs baseline: 2.3521x; 1.1572x over previous
#include <cuda_runtime.h>
#include <cuda_fp16.h>
#include <math.h>
#include <stdint.h>

#define NTOK 65536
#define DDIM 128
#define NEXP 16
#define TOPK 3

#define KPAD 136              // fp16 elements per padded row
#define ROWB 272              // bytes per padded row
#define GEMM_GX 32            // grid.x for moe_gemm (tiles strided per CTA)

// ---------------------------------------------------------------------------
// Device globals
// ---------------------------------------------------------------------------
__device__ int      g_cnt[NEXP];
__device__ unsigned g_list[NEXP * NTOK];                 // (token<<2)|slot
__device__ float    g_wlist[NEXP * NTOK];
__device__ __half   g_Bh[NEXP * DDIM * KPAD];            // padded fp16 [e][n][k]
__device__ __half   g_ybuf[(size_t)NTOK * TOPK * DDIM];  // 24MB fp16 partials
__device__ uint4    g_topk[NTOK];                        // {i0|i1<<8|i2<<16, w0, w1, w2}
__device__ float    g_part[512 * NEXP];                  // per-gating-block imp partials

// ---------------------------------------------------------------------------
// helpers
// ---------------------------------------------------------------------------
__device__ __forceinline__ uint32_t smem_u32(const void* p) {
    uint32_t a;
    asm("{ .reg .u64 t; cvta.to.shared.u64 t, %1; cvt.u32.u64 %0, t; }" : "=r"(a) : "l"(p));
    return a;
}

#define LDSM_X4(r0, r1, r2, r3, addr) \
    asm volatile("ldmatrix.sync.aligned.m8n8.x4.shared.b16 {%0,%1,%2,%3}, [%4];" \
                 : "=r"(r0), "=r"(r1), "=r"(r2), "=r"(r3) : "r"(addr))

__device__ __forceinline__ void mma16816(float* c,
    uint32_t a0, uint32_t a1, uint32_t a2, uint32_t a3, uint32_t b0, uint32_t b1)
{
    asm volatile(
        "mma.sync.aligned.m16n8k16.row.col.f32.f16.f16.f32 "
        "{%0,%1,%2,%3}, {%4,%5,%6,%7}, {%8,%9}, {%0,%1,%2,%3};"
        : "+f"(c[0]), "+f"(c[1]), "+f"(c[2]), "+f"(c[3])
        : "r"(a0), "r"(a1), "r"(a2), "r"(a3), "r"(b0), "r"(b1));
}

// ---------------------------------------------------------------------------
// prepB: padded fp16 image of We^T ([e][n][k] row-major). Zeroes g_cnt.
// grid (16, 4) x 256
// ---------------------------------------------------------------------------
__global__ void __launch_bounds__(256) prepB_kernel(const float* __restrict__ We)
{
    if (blockIdx.x == 0 && blockIdx.y == 0 && threadIdx.x < NEXP)
        g_cnt[threadIdx.x] = 0;

    int e = blockIdx.x;
    const float* W = We + (size_t)e * DDIM * DDIM;
    __half* dst = g_Bh + (size_t)e * DDIM * KPAD;
    int i0 = blockIdx.y * 2048 + threadIdx.x;
    for (int i = i0; i < (blockIdx.y + 1) * 2048; i += 256) {
        int n = i >> 6, kp = i & 63, k = kp * 2;
        __half2 hp;
        hp.x = __float2half(W[k * DDIM + n]);
        hp.y = __float2half(W[(k + 1) * DDIM + n]);
        *(__half2*)(dst + n * KPAD + k) = hp;
    }
}

// ---------------------------------------------------------------------------
// Gating: gate = x@Wg + bg + noise*softplus(x@Wn+bn); top-3; softmax -> comb,
// g_topk, routing lists, and per-block importance partials. grid 512 x 128
// ---------------------------------------------------------------------------
__global__ void __launch_bounds__(128) gating_kernel(
    const float* __restrict__ x, const float* __restrict__ noise,
    const float* __restrict__ Wg, const float* __restrict__ bg,
    const float* __restrict__ Wn, const float* __restrict__ bn,
    float* __restrict__ comb)
{
    __shared__ float WgT[NEXP * DDIM];
    __shared__ float WnT[NEXP * DDIM];
    __shared__ float tw[128][3];
    __shared__ int   ti[128][3];
    __shared__ int   scnt16[NEXP];
    __shared__ int   gbase[NEXP];
    __shared__ float sred[NEXP][8];

    int tid = threadIdx.x;
    if (tid < NEXP) scnt16[tid] = 0;
    for (int i = tid; i < NEXP * DDIM; i += 128) {
        int d = i / NEXP, e = i % NEXP;
        WgT[e * DDIM + d] = Wg[i];
        WnT[e * DDIM + d] = Wn[i];
    }
    __syncthreads();

    int n = blockIdx.x * 128 + tid;

    float g[NEXP], ng[NEXP];
    #pragma unroll
    for (int e = 0; e < NEXP; e++) { g[e] = bg[e]; ng[e] = bn[e]; }

    const float4* x4 = (const float4*)(x + (size_t)n * DDIM);
    #pragma unroll 2
    for (int d4 = 0; d4 < DDIM / 4; d4++) {
        float4 xv = x4[d4];
        #pragma unroll
        for (int e = 0; e < NEXP; e++) {
            float4 a = ((const float4*)(WgT + e * DDIM))[d4];
            g[e]  += xv.x * a.x + xv.y * a.y + xv.z * a.z + xv.w * a.w;
            float4 b = ((const float4*)(WnT + e * DDIM))[d4];
            ng[e] += xv.x * b.x + xv.y * b.y + xv.z * b.z + xv.w * b.w;
        }
    }

    const float* nz = noise + (size_t)n * NEXP;
    #pragma unroll
    for (int e = 0; e < NEXP; e++) {
        float v = ng[e];
        float sp = (v > 20.f) ? v : log1pf(expf(v));
        g[e] = g[e] + nz[e] * sp;
    }

    float v0 = -INFINITY, v1 = -INFINITY, v2 = -INFINITY;
    int i0 = 0, i1 = 0, i2 = 0;
    #pragma unroll
    for (int e = 0; e < NEXP; e++) {
        float v = g[e];
        if (v > v0)      { v2 = v1; i2 = i1; v1 = v0; i1 = i0; v0 = v; i0 = e; }
        else if (v > v1) { v2 = v1; i2 = i1; v1 = v;  i1 = e; }
        else if (v > v2) { v2 = v;  i2 = e; }
    }

    float e1 = expf(v1 - v0), e2 = expf(v2 - v0);
    float s = 1.f + e1 + e2;
    float w0 = 1.f / s, w1 = e1 / s, w2 = e2 / s;

    int p0 = atomicAdd(&scnt16[i0], 1);
    int p1 = atomicAdd(&scnt16[i1], 1);
    int p2 = atomicAdd(&scnt16[i2], 1);

    tw[tid][0] = w0; tw[tid][1] = w1; tw[tid][2] = w2;
    ti[tid][0] = i0; ti[tid][1] = i1; ti[tid][2] = i2;

    // packed topk record for combine
    {
        uint4 tk;
        tk.x = (unsigned)i0 | ((unsigned)i1 << 8) | ((unsigned)i2 << 16);
        tk.y = __float_as_uint(w0);
        tk.z = __float_as_uint(w1);
        tk.w = __float_as_uint(w2);
        g_topk[n] = tk;
    }
    __syncthreads();

    if (tid < NEXP) gbase[tid] = atomicAdd(&g_cnt[tid], scnt16[tid]);
    __syncthreads();

    {
        int q0 = gbase[i0] + p0;
        int q1 = gbase[i1] + p1;
        int q2 = gbase[i2] + p2;
        g_list[i0 * NTOK + q0] = ((unsigned)n << 2) | 0u;  g_wlist[i0 * NTOK + q0] = w0;
        g_list[i1 * NTOK + q1] = ((unsigned)n << 2) | 1u;  g_wlist[i1 * NTOK + q1] = w1;
        g_list[i2 * NTOK + q2] = ((unsigned)n << 2) | 2u;  g_wlist[i2 * NTOK + q2] = w2;
    }

    int base = blockIdx.x * 128;
    // scalar comb writes (comb region only 4B aligned)
    for (int i = tid; i < 128 * NEXP; i += 128) {
        int t = i >> 4, e = i & 15;
        float v = (e == ti[t][0]) ? tw[t][0]
                : (e == ti[t][1]) ? tw[t][1]
                : (e == ti[t][2]) ? tw[t][2] : 0.f;
        comb[(size_t)(base + t) * NEXP + e] = v;
    }

    // deterministic importance partials: expert e <- 8 threads, 16 tokens each
    {
        int e = tid & 15, j = tid >> 4;
        float ps = 0.f;
        int t0 = j * 16;
        #pragma unroll 4
        for (int t = t0; t < t0 + 16; t++) {
            if (ti[t][0] == e) ps += tw[t][0];
            if (ti[t][1] == e) ps += tw[t][1];
            if (ti[t][2] == e) ps += tw[t][2];
        }
        sred[e][j] = ps;
    }
    __syncthreads();
    if (tid < NEXP) {
        float s2 = 0.f;
        #pragma unroll
        for (int j = 0; j < 8; j++) s2 += sred[tid][j];
        g_part[blockIdx.x * NEXP + tid] = s2;
    }
}

// ---------------------------------------------------------------------------
// MoE GEMM via mma.sync fp16 (f32 accum). grid (GEMM_GX, NEXP) x 256.
// Each CTA strides over ~ntile/GEMM_GX 128-token tiles (B staged once).
// smem: A[0,34816) B[34816,69632) ent[69632,+512) w[+512)  => 70656 bytes
// ---------------------------------------------------------------------------
#define SM_A   0
#define SM_B   34816
#define SM_ENT 69632
#define SM_W   70144
#define SM_SZ  70656

__global__ void __launch_bounds__(256, 2) moe_gemm_kernel(const float* __restrict__ x)
{
    extern __shared__ char smp[];
    uint32_t base = smem_u32(smp);

    int tid = threadIdx.x, wp = tid >> 5, ln = tid & 31;
    int e = blockIdx.y;
    int cnt = g_cnt[e];
    int ntile = (cnt + 127) >> 7;
    if ((int)blockIdx.x >= ntile) return;

    // stage fp16 B image (plain copy, padded rows)
    {
        const float4* bs = (const float4*)(g_Bh + (size_t)e * DDIM * KPAD);
        float4* bd = (float4*)(smp + SM_B);
        #pragma unroll 4
        for (int i = tid; i < DDIM * ROWB / 16; i += 256) bd[i] = bs[i];
    }

    unsigned* entS = (unsigned*)(smp + SM_ENT);
    float*    wS   = (float*)(smp + SM_W);

    int mrow = (wp & 3) * 32;
    int ncol = (wp >> 2) * 64;

    uint32_t a_off = (uint32_t)(mrow + (ln & 15)) * ROWB + ((ln >> 4) << 4);
    uint32_t b_off = (uint32_t)(ncol + (ln & 7) + ((ln >> 4) << 3)) * ROWB + (((ln >> 3) & 1) << 4);

    for (int t = blockIdx.x; t < ntile; t += GEMM_GX) {
        int rbase = t << 7;
        int mvalid = min(128, cnt - rbase);

        if (tid < 128) {
            if (tid < mvalid) {
                entS[tid] = g_list[e * NTOK + rbase + tid];
                wS[tid]   = g_wlist[e * NTOK + rbase + tid];
            } else { entS[tid] = 0xFFFFFFFFu; wS[tid] = 0.f; }
        }
        __syncthreads();

        // build A panel (gather + fp16 cvt)
        for (int i = tid; i < 8192; i += 256) {
            int m = i >> 6, kp = i & 63;
            unsigned en = entS[m];
            uint32_t hv = 0;
            if (en != 0xFFFFFFFFu) {
                float2 v = *(const float2*)(x + (size_t)(en >> 2) * DDIM + kp * 2);
                __half2 hp; hp.x = __float2half(v.x); hp.y = __float2half(v.y);
                hv = *(uint32_t*)&hp;
            }
            *(uint32_t*)(smp + SM_A + (uint32_t)m * ROWB + (uint32_t)kp * 4) = hv;
        }
        __syncthreads();

        float c[2][8][4];
        #pragma unroll
        for (int i = 0; i < 2; i++)
            #pragma unroll
            for (int j = 0; j < 8; j++)
                #pragma unroll
                for (int q = 0; q < 4; q++) c[i][j][q] = 0.f;

        uint32_t ab = base + SM_A + a_off;
        uint32_t bb = base + SM_B + b_off;
        #pragma unroll
        for (int kk = 0; kk < 8; kk++) {
            uint32_t kb = (uint32_t)kk * 32;
            uint32_t a0, a1, a2, a3, a4, a5, a6, a7;
            LDSM_X4(a0, a1, a2, a3, ab + kb);
            LDSM_X4(a4, a5, a6, a7, ab + 16 * ROWB + kb);
            #pragma unroll
            for (int nw = 0; nw < 4; nw++) {
                uint32_t b0, b1, b2, b3;
                LDSM_X4(b0, b1, b2, b3, bb + (uint32_t)nw * 16 * ROWB + kb);
                mma16816(c[0][nw * 2 + 0], a0, a1, a2, a3, b0, b1);
                mma16816(c[0][nw * 2 + 1], a0, a1, a2, a3, b2, b3);
                mma16816(c[1][nw * 2 + 0], a4, a5, a6, a7, b0, b1);
                mma16816(c[1][nw * 2 + 1], a4, a5, a6, a7, b2, b3);
            }
        }

        // epilogue: scale by routing weight, fp16 store to ybuf
        {
            int gid = ln >> 2, tig = ln & 3;
            #pragma unroll
            for (int mt = 0; mt < 2; mt++) {
                int r0 = mrow + mt * 16 + gid;
                int r1 = r0 + 8;
                unsigned e0 = entS[r0], e1 = entS[r1];
                float wa = wS[r0], wb = wS[r1];
                __half* y0 = g_ybuf + ((size_t)(e0 >> 2) * 3 + (e0 & 3u)) * DDIM;
                __half* y1 = g_ybuf + ((size_t)(e1 >> 2) * 3 + (e1 & 3u)) * DDIM;
                #pragma unroll
                for (int nt = 0; nt < 8; nt++) {
                    int col = ncol + nt * 8 + tig * 2;
                    if (e0 != 0xFFFFFFFFu) {
                        __half2 hv;
                        hv.x = __float2half(c[mt][nt][0] * wa);
                        hv.y = __float2half(c[mt][nt][1] * wa);
                        *(__half2*)(y0 + col) = hv;
                    }
                    if (e1 != 0xFFFFFFFFu) {
                        __half2 hv;
                        hv.x = __float2half(c[mt][nt][2] * wb);
                        hv.y = __float2half(c[mt][nt][3] * wb);
                        *(__half2*)(y1 + col) = hv;
                    }
                }
            }
        }
        __syncthreads();
    }
}

// ---------------------------------------------------------------------------
// Combine: logits[n] = sum_k w_k*be[e_k] + ybuf[n][0]+[1]+[2]
// grid 1024 x 256. One warp handles one token row per iteration (lane = float4).
// ---------------------------------------------------------------------------
__global__ void __launch_bounds__(256) combine_kernel(
    const float* __restrict__ be, float* __restrict__ logits)
{
    __shared__ float beS[NEXP][DDIM];   // 8KB

    int tid = threadIdx.x;
    int n0 = blockIdx.x * 64;

    for (int i = tid; i < NEXP * DDIM; i += 256) beS[i >> 7][i & 127] = be[i];
    __syncthreads();

    #pragma unroll
    for (int k = 0; k < 8; k++) {
        int i = k * 256 + tid;              // over 64 tokens x 32 float4
        int n = n0 + (i >> 5), c4 = i & 31;
        int col = c4 * 4;

        uint4 tk = g_topk[n];               // warp-uniform (whole warp = one token)
        int i0 = tk.x & 255, i1 = (tk.x >> 8) & 255, i2 = (tk.x >> 16) & 255;
        float w0 = __uint_as_float(tk.y);
        float w1 = __uint_as_float(tk.z);
        float w2 = __uint_as_float(tk.w);

        const __half* y = g_ybuf + (size_t)n * 3 * DDIM;
        float4 a;
        {
            __half2 p0 = *(const __half2*)(y + col);
            __half2 p1 = *(const __half2*)(y + col + 2);
            __half2 q0 = *(const __half2*)(y + DDIM + col);
            __half2 q1 = *(const __half2*)(y + DDIM + col + 2);
            __half2 r0 = *(const __half2*)(y + 2 * DDIM + col);
            __half2 r1 = *(const __half2*)(y + 2 * DDIM + col + 2);
            float2 f0 = __half22float2(p0), f1 = __half22float2(p1);
            float2 g0 = __half22float2(q0), g1 = __half22float2(q1);
            float2 h0 = __half22float2(r0), h1 = __half22float2(r1);
            a.x = f0.x + g0.x + h0.x;
            a.y = f0.y + g0.y + h0.y;
            a.z = f1.x + g1.x + h1.x;
            a.w = f1.y + g1.y + h1.y;
        }
        // 3-term bias
        {
            const float4 b0 = *(const float4*)(&beS[i0][col]);
            const float4 b1 = *(const float4*)(&beS[i1][col]);
            const float4 b2 = *(const float4*)(&beS[i2][col]);
            a.x += w0 * b0.x + w1 * b1.x + w2 * b2.x;
            a.y += w0 * b0.y + w1 * b1.y + w2 * b2.y;
            a.z += w0 * b0.z + w1 * b1.z + w2 * b2.z;
            a.w += w0 * b0.w + w1 * b1.w + w2 * b2.w;
        }
        *(float4*)(logits + (size_t)n * DDIM + col) = a;
    }
}

// ---------------------------------------------------------------------------
// Loss: sum 512 per-block partials per expert -> (std(ddof=1)/mean)^2
// 1 block x 256
// ---------------------------------------------------------------------------
__global__ void loss_kernel(const float* __restrict__ part, float* __restrict__ out_loss)
{
    __shared__ float red[NEXP][17];
    int tid = threadIdx.x;
    int e = tid >> 4, j = tid & 15;
    float s = 0.f;
    for (int k = 0; k < 32; k++) s += part[(j * 32 + k) * NEXP + e];
    red[e][j] = s;
    __syncthreads();
    if (tid < NEXP) {
        float t = 0.f;
        #pragma unroll
        for (int q = 0; q < 16; q++) t += red[tid][q];
        red[tid][16] = t;
    }
    __syncthreads();
    if (tid == 0) {
        float mean = 0.f;
        for (int e2 = 0; e2 < NEXP; e2++) mean += red[e2][16];
        mean /= (float)NEXP;
        float var = 0.f;
        for (int e2 = 0; e2 < NEXP; e2++) {
            float d = red[e2][16] - mean;
            var += d * d;
        }
        var /= (float)(NEXP - 1);
        out_loss[0] = var / (mean * mean);
    }
}

// ---------------------------------------------------------------------------
extern "C" void kernel_launch(void* const* d_in, const int* in_sizes, int n_in,
                              void* d_out, int out_size)
{
    const float* x     = (const float*)d_in[0];
    const float* noise = (const float*)d_in[1];
    const float* Wg    = (const float*)d_in[2];
    const float* bg    = (const float*)d_in[3];
    const float* Wn    = (const float*)d_in[4];
    const float* bn    = (const float*)d_in[5];
    const float* We    = (const float*)d_in[6];
    const float* be    = (const float*)d_in[7];

    float* out    = (float*)d_out;
    float* logits = out;                               // [N, D]
    float* lossp  = out + (size_t)NTOK * DDIM;         // scalar
    float* comb   = lossp + 1;                         // [N, E] (4B aligned only)

    float* part;  cudaGetSymbolAddress((void**)&part, g_part);

    prepB_kernel<<<dim3(NEXP, 4), 256>>>(We);          // also zeroes g_cnt

    gating_kernel<<<NTOK / 128, 128>>>(x, noise, Wg, bg, Wn, bn, comb);

    cudaFuncSetAttribute(moe_gemm_kernel,
                         cudaFuncAttributeMaxDynamicSharedMemorySize, SM_SZ);
    moe_gemm_kernel<<<dim3(GEMM_GX, NEXP), 256, SM_SZ>>>(x);

    combine_kernel<<<NTOK / 64, 256>>>(be, logits);

    loss_kernel<<<1, 256>>>(part, lossp);

    (void)in_sizes; (void)n_in; (void)out_size;
}